// round 13
// baseline (speedup 1.0000x reference)
#include <cuda_runtime.h>
#include <cuda_bf16.h>
#include <cstdint>

// Trajectory signature kernel, v7: warp-decoupled cp.async streaming.
// No __syncthreads in the main loop: each of the 8 warps owns a contiguous
// 256-row segment of the trajectory and streams it through its own 3-slot
// ring of 64-row sub-tiles (warp-local commit groups, __syncwarp only).
// Compute body identical to v4 (adjacent-row pairs, 9x LDS.64/thread).
// Input:  trajectories [4096, 2048, 6] fp32 (row-major)
// Output: [4096, 5] fp32

#define T_LEN    2048
#define N_TRAJ   4096
#define N_WARPS  8
#define W_ROWS   256                      // rows per warp segment
#define ST_ROWS  64                       // rows per sub-tile
#define NST      (W_ROWS / ST_ROWS)       // 4
#define ST_F4    (ST_ROWS * 6 / 4)        // 96 float4 per sub-tile
#define HALO_W   8                        // halo words [2..7] hold prev row
#define SB_WORDS (HALO_W + ST_ROWS * 6)   // 392
#define EPS_NORM 1e-6f
#define EPS_MEAN 1e-6f

__device__ __forceinline__ float warp_sum(float x) {
    #pragma unroll
    for (int o = 16; o > 0; o >>= 1)
        x += __shfl_down_sync(0xffffffffu, x, o);
    return x;
}

__device__ __forceinline__ unsigned int smem_u32(const void* p) {
    unsigned int a;
    asm("{ .reg .u64 t; cvta.to.shared.u64 t, %1; cvt.u32.u64 %0, t; }"
        : "=r"(a) : "l"(p));
    return a;
}

#define CP_ASYNC16(dst_u32, src_ptr) \
    asm volatile("cp.async.cg.shared.global [%0], [%1], 16;" \
                 :: "r"(dst_u32), "l"(src_ptr) : "memory")
#define CP_COMMIT() asm volatile("cp.async.commit_group;" ::: "memory")
#define CP_WAIT(n)  asm volatile("cp.async.wait_group %0;" :: "n"(n) : "memory")

__global__ __launch_bounds__(256, 6) void signature_kernel(
    const float4* __restrict__ trajv, float* __restrict__ out)
{
    __shared__ __align__(16) float sb[N_WARPS][3][SB_WORDS];  // 36.75 KB
    __shared__ float red[N_WARPS][8];

    const int tid  = threadIdx.x;
    const int lane = tid & 31;
    const int w    = tid >> 5;
    const int tr   = blockIdx.x;

    // this warp's global float4 base: trajectory + w*256 rows
    const float4* wbase = trajv + (size_t)tr * (T_LEN * 6 / 4) + w * (W_ROWS * 6 / 4);

    // per-slot smem byte address of this lane's first float4 slot
    unsigned int dstb[3];
    #pragma unroll
    for (int b = 0; b < 3; ++b)
        dstb[b] = smem_u32(&sb[w][b][HALO_W + 4 * lane]);

    // prologue: issue sub-tiles 0 and 1 (one commit group each)
    #pragma unroll
    for (int s = 0; s < 2; ++s) {
        const float4* src = wbase + s * ST_F4 + lane;
        CP_ASYNC16(dstb[s],            src);
        CP_ASYNC16(dstb[s] + 32 * 16,  src + 32);
        CP_ASYNC16(dstb[s] + 64 * 16,  src + 64);
        CP_COMMIT();
    }

    // segment-start halo: row w*256-1 (last row of previous warp's segment),
    // loaded straight from global by lane 0 into slot 0's halo words [2..7].
    if (w > 0 && lane == 0) {
        const float2* gp = reinterpret_cast<const float2*>(trajv) +
                           ((size_t)tr * (T_LEN * 3)) + (w * (W_ROWS * 3)) - 3;
        float2 h0 = gp[0], h1 = gp[1], h2 = gp[2];
        float2* hp = reinterpret_cast<float2*>(&sb[w][0][2]);
        hp[0] = h0; hp[1] = h1; hp[2] = h2;
    }

    float s_curv = 0.f, cnt = 0.f;
    float s_vd = 0.f, s_ad = 0.f;
    float s_sp = 0.f, s_sp2 = 0.f;
    float s_f  = 0.f, s_f2  = 0.f;

    #pragma unroll
    for (int s = 0; s < NST; ++s) {
        // sub-tile s arrived: allow 1 pending group except on the last
        if (s < NST - 1) { CP_WAIT(1); } else { CP_WAIT(0); }
        __syncwarp();    // cross-lane visibility of cp.async data + halo STS

        const int cb = s % 3;
        float* cbuf = sb[w][cb];

        // issue sub-tile s+2 into slot (s+2)%3 (overlaps compute below)
        if (s + 2 < NST) {
            const int nb = (s + 2) % 3;
            const float4* src = wbase + (s + 2) * ST_F4 + lane;
            CP_ASYNC16(dstb[nb],           src);
            CP_ASYNC16(dstb[nb] + 32 * 16, src + 32);
            CP_ASYNC16(dstb[nb] + 64 * 16, src + 64);
            CP_COMMIT();
        }

        // compute rows 2*lane, 2*lane+1 of this sub-tile (v4 body).
        // 18 contiguous words: prev row | row0 | row1 (float2-aligned)
        const float2* rp = reinterpret_cast<const float2*>(
            &cbuf[HALO_W + 12 * lane - 6]);   // lane==0 -> halo words [2..7]
        const float2 pp = rp[0], pv = rp[1], pa = rp[2];   // prev row
        const float2 p0 = rp[3], v0 = rp[4], a0 = rp[5];   // row 2*lane
        const float2 p1 = rp[6], v1 = rp[7], a1 = rp[8];   // row 2*lane+1

        // halo for sub-tile s+1: lane 31's row1 is its last row
        if (s + 1 < NST && lane == 31) {
            float2* hp = reinterpret_cast<float2*>(&sb[w][(s + 1) % 3][2]);
            hp[0] = p1; hp[1] = v1; hp[2] = a1;
        }

        // per-row moments (both rows, always valid)
        const float sp0 = sqrtf(v0.x * v0.x + v0.y * v0.y);
        const float sp1 = sqrtf(v1.x * v1.x + v1.y * v1.y);
        const float fo0 = sqrtf(a0.x * a0.x + a0.y * a0.y);
        const float fo1 = sqrtf(a1.x * a1.x + a1.y * a1.y);
        s_sp  += sp0 + sp1;
        s_sp2 = fmaf(sp0, sp0, s_sp2); s_sp2 = fmaf(sp1, sp1, s_sp2);
        s_f   += fo0 + fo1;
        s_f2  = fmaf(fo0, fo0, s_f2);  s_f2  = fmaf(fo1, fo1, s_f2);

        const float nsq0 = p0.x * p0.x + p0.y * p0.y;
        const float nsq1 = p1.x * p1.x + p1.y * p1.y;

        // row1 <- row0 diffs (always valid: global r odd >= 1)
        s_vd += fabsf(v1.x - v0.x) + fabsf(v1.y - v0.y);
        s_ad += fabsf(a1.x - a0.x) + fabsf(a1.y - a0.y);

        // rows 0/1 of the whole trajectory excluded for row0<-prev terms
        const bool nf = (w > 0) | (s > 0) | (lane > 0);
        if (nf) {
            s_vd += fabsf(v0.x - pv.x) + fabsf(v0.y - pv.y);
            s_ad += fabsf(a0.x - pa.x) + fabsf(a0.y - pa.y);

            const float nsqp = pp.x * pp.x + pp.y * pp.y;
            const float cr0  = pp.x * p0.y - pp.y * p0.x;
            const float pr0  = nsqp * nsq0;
            if (pr0 > EPS_NORM * EPS_NORM) {
                s_curv = fmaf(fabsf(cr0), rsqrtf(pr0), s_curv);
                cnt += 1.0f;
            }
            const float cr1 = p0.x * p1.y - p0.y * p1.x;
            const float pr1 = nsq0 * nsq1;
            if (pr1 > EPS_NORM * EPS_NORM) {
                s_curv = fmaf(fabsf(cr1), rsqrtf(pr1), s_curv);
                cnt += 1.0f;
            }
        }
    }

    // intra-warp reductions
    s_curv = warp_sum(s_curv);
    cnt    = warp_sum(cnt);
    s_vd   = warp_sum(s_vd);
    s_ad   = warp_sum(s_ad);
    s_sp   = warp_sum(s_sp);
    s_sp2  = warp_sum(s_sp2);
    s_f    = warp_sum(s_f);
    s_f2   = warp_sum(s_f2);

    if (lane == 0) {
        red[w][0] = s_curv; red[w][1] = cnt;
        red[w][2] = s_vd;   red[w][3] = s_ad;
        red[w][4] = s_sp;   red[w][5] = s_sp2;
        red[w][6] = s_f;    red[w][7] = s_f2;
    }
    __syncthreads();

    if (tid == 0) {
        float t_curv = 0.f, t_cnt = 0.f, t_vd = 0.f, t_ad = 0.f;
        float t_sp = 0.f, t_sp2 = 0.f, t_f = 0.f, t_f2 = 0.f;
        #pragma unroll
        for (int k = 0; k < N_WARPS; ++k) {
            t_curv += red[k][0]; t_cnt += red[k][1];
            t_vd   += red[k][2]; t_ad  += red[k][3];
            t_sp   += red[k][4]; t_sp2 += red[k][5];
            t_f    += red[k][6]; t_f2  += red[k][7];
        }

        const float path_curvature = (t_cnt > 0.f) ? (t_curv / t_cnt) : 0.f;

        const float denom = 2.0f * (float)(T_LEN - 1);
        const float velocity_smoothness = 1.0f / (1.0f + t_vd / denom);
        const float acceleration_jerk   = t_ad / denom;

        const float msp = t_sp / (float)T_LEN;
        float var_sp = t_sp2 / (float)T_LEN - msp * msp;
        if (var_sp < 0.f) var_sp = 0.f;
        const float movement_rhythm = sqrtf(var_sp) / (msp + EPS_MEAN);

        const float mf = t_f / (float)T_LEN;
        float var_f = t_f2 / (float)T_LEN - mf * mf;
        if (var_f < 0.f) var_f = 0.f;
        const float force_modulation = sqrtf(var_f) / (mf + EPS_MEAN);

        float* o = out + tr * 5;
        o[0] = path_curvature;
        o[1] = velocity_smoothness;
        o[2] = acceleration_jerk;
        o[3] = movement_rhythm;
        o[4] = force_modulation;
    }
}

extern "C" void kernel_launch(void* const* d_in, const int* in_sizes, int n_in,
                              void* d_out, int out_size) {
    const float4* traj = (const float4*)d_in[0];
    float* out = (float*)d_out;
    signature_kernel<<<N_TRAJ, 256>>>(traj, out);
}

// round 14
// speedup vs baseline: 1.2328x; 1.2328x over previous
#include <cuda_runtime.h>
#include <cuda_bf16.h>
#include <cstdint>

// Trajectory signature kernel, v8: v4 skeleton (cp.async triple buffer,
// depth-2, 512-row tiles, occ 6) + conflict-free uniform LDS.128 reads.
// Thread t reads its prev-row+row-pair block as 1 LDS.64 + 4 LDS.128
// (slots 3t-1..3t+2, coprime with 8 -> no bank-group conflicts), no
// shuffles, no divergent lanes. MIO cost/warp-tile: 72 -> 24 cyc.
// Input:  trajectories [4096, 2048, 6] fp32 (row-major)
// Output: [4096, 5] fp32

#define T_LEN   2048
#define N_TRAJ  4096
#define TILE    512
#define NT      (T_LEN / TILE)            // 4
#define F4_PER_TILE (TILE * 6 / 4)        // 768
#define HALO_W  8                         // halo row at words [2..7]
#define BUF_WORDS (HALO_W + TILE * 6)     // 3080 words
#define EPS_NORM 1e-6f
#define EPS_MEAN 1e-6f

__device__ __forceinline__ float warp_sum(float x) {
    #pragma unroll
    for (int o = 16; o > 0; o >>= 1)
        x += __shfl_down_sync(0xffffffffu, x, o);
    return x;
}

__device__ __forceinline__ unsigned int smem_u32(const void* p) {
    unsigned int a;
    asm("{ .reg .u64 t; cvta.to.shared.u64 t, %1; cvt.u32.u64 %0, t; }"
        : "=r"(a) : "l"(p));
    return a;
}

#define CP_ASYNC16(dst_u32, src_ptr) \
    asm volatile("cp.async.cg.shared.global [%0], [%1], 16;" \
                 :: "r"(dst_u32), "l"(src_ptr) : "memory")
#define CP_COMMIT() asm volatile("cp.async.commit_group;" ::: "memory")
#define CP_WAIT(n)  asm volatile("cp.async.wait_group %0;" :: "n"(n) : "memory")

__global__ __launch_bounds__(256, 6) void signature_kernel(
    const float4* __restrict__ trajv, float* __restrict__ out)
{
    __shared__ __align__(16) float sb[3][BUF_WORDS];
    __shared__ float red[8][8];

    const int tid = threadIdx.x;
    const int tr  = blockIdx.x;
    const float4* base = trajv + (size_t)tr * (T_LEN * 6 / 4);

    // per-buffer smem byte address of float4 slot `tid` (word HALO_W + 4*tid)
    unsigned int dstb[3];
    #pragma unroll
    for (int b = 0; b < 3; ++b)
        dstb[b] = smem_u32(&sb[b][HALO_W + 4 * tid]);

    // prologue: issue tiles 0 and 1
    #pragma unroll
    for (int t = 0; t < 2; ++t) {
        const float4* src = base + t * F4_PER_TILE + tid;
        CP_ASYNC16(dstb[t],               src);
        CP_ASYNC16(dstb[t] + 256 * 16,    src + 256);
        CP_ASYNC16(dstb[t] + 512 * 16,    src + 512);
        CP_COMMIT();
    }

    float s_curv = 0.f, cnt = 0.f;
    float s_vd = 0.f, s_ad = 0.f;
    float s_sp = 0.f, s_sp2 = 0.f;
    float s_f  = 0.f, s_f2  = 0.f;

    #pragma unroll
    for (int t = 0; t < NT; ++t) {
        if (t == NT - 1) { CP_WAIT(0); } else { CP_WAIT(1); }
        __syncthreads();   // tile-t data visible to all; buf (t+2)%3 free

        const int cb = t % 3;
        float* cbuf = sb[cb];

        // issue tile t+2 into buffer (t+2)%3 (overlaps compute below)
        if (t + 2 < NT) {
            const int nb2 = (t + 2) % 3;
            const float4* src = base + (t + 2) * F4_PER_TILE + tid;
            CP_ASYNC16(dstb[nb2],            src);
            CP_ASYNC16(dstb[nb2] + 256 * 16, src + 256);
            CP_ASYNC16(dstb[nb2] + 512 * 16, src + 512);
            CP_COMMIT();
        }

        // halo for tile t+1: copy last row of tile t into next buffer's halo
        if (t + 1 < NT && tid < 6)
            sb[(t + 1) % 3][2 + tid] = cbuf[HALO_W + (TILE - 1) * 6 + tid];

        // ---- compute rows 2*tid, 2*tid+1 ----
        // Block words 12t-6 .. 12t+11 (prev row | row0 | row1) read as:
        //   LDS.64  @ 12t-6 : pp                      (4-way conflict, cheap)
        //   LDS.128 @ slots 3t-1,3t,3t+1,3t+2 : conflict-free (3t+k mod 8)
        const float* bw = &cbuf[HALO_W + 12 * tid];
        const float2 pp = *reinterpret_cast<const float2*>(bw - 6);
        const float4 qa = *reinterpret_cast<const float4*>(bw - 4); // pv,pa
        const float4 q0 = *reinterpret_cast<const float4*>(bw);     // p0,v0
        const float4 q1 = *reinterpret_cast<const float4*>(bw + 4); // a0,p1
        const float4 q2 = *reinterpret_cast<const float4*>(bw + 8); // v1,a1

        const float2 pv = make_float2(qa.x, qa.y), pa = make_float2(qa.z, qa.w);
        const float2 p0 = make_float2(q0.x, q0.y), v0 = make_float2(q0.z, q0.w);
        const float2 a0 = make_float2(q1.x, q1.y), p1 = make_float2(q1.z, q1.w);
        const float2 v1 = make_float2(q2.x, q2.y), a1 = make_float2(q2.z, q2.w);

        // per-row moments (both rows, always valid)
        const float sp0 = sqrtf(v0.x * v0.x + v0.y * v0.y);
        const float sp1 = sqrtf(v1.x * v1.x + v1.y * v1.y);
        const float fo0 = sqrtf(a0.x * a0.x + a0.y * a0.y);
        const float fo1 = sqrtf(a1.x * a1.x + a1.y * a1.y);
        s_sp  += sp0 + sp1;
        s_sp2 = fmaf(sp0, sp0, s_sp2); s_sp2 = fmaf(sp1, sp1, s_sp2);
        s_f   += fo0 + fo1;
        s_f2  = fmaf(fo0, fo0, s_f2);  s_f2  = fmaf(fo1, fo1, s_f2);

        const float nsq0 = p0.x * p0.x + p0.y * p0.y;
        const float nsq1 = p1.x * p1.x + p1.y * p1.y;

        // row1 <- row0 diffs (global r = 512t+2*tid+1 >= 1 always)
        s_vd += fabsf(v1.x - v0.x) + fabsf(v1.y - v0.y);
        s_ad += fabsf(a1.x - a0.x) + fabsf(a1.y - a0.y);

        const bool nf = (t > 0) | (tid > 0);   // rows 0/1 of trajectory excluded
        if (nf) {
            // row0 <- prev diffs
            s_vd += fabsf(v0.x - pv.x) + fabsf(v0.y - pv.y);
            s_ad += fabsf(a0.x - pa.x) + fabsf(a0.y - pa.y);

            // curvature row0 (v1=prev pos delta, v2=row0 pos delta)
            const float nsqp = pp.x * pp.x + pp.y * pp.y;
            const float cr0  = pp.x * p0.y - pp.y * p0.x;
            const float pr0  = nsqp * nsq0;
            if (pr0 > EPS_NORM * EPS_NORM) {
                s_curv = fmaf(fabsf(cr0), rsqrtf(pr0), s_curv);
                cnt += 1.0f;
            }
            // curvature row1
            const float cr1 = p0.x * p1.y - p0.y * p1.x;
            const float pr1 = nsq0 * nsq1;
            if (pr1 > EPS_NORM * EPS_NORM) {
                s_curv = fmaf(fabsf(cr1), rsqrtf(pr1), s_curv);
                cnt += 1.0f;
            }
        }
    }

    // reductions
    s_curv = warp_sum(s_curv);
    cnt    = warp_sum(cnt);
    s_vd   = warp_sum(s_vd);
    s_ad   = warp_sum(s_ad);
    s_sp   = warp_sum(s_sp);
    s_sp2  = warp_sum(s_sp2);
    s_f    = warp_sum(s_f);
    s_f2   = warp_sum(s_f2);

    const int lane = tid & 31;
    const int wid  = tid >> 5;
    if (lane == 0) {
        red[wid][0] = s_curv; red[wid][1] = cnt;
        red[wid][2] = s_vd;   red[wid][3] = s_ad;
        red[wid][4] = s_sp;   red[wid][5] = s_sp2;
        red[wid][6] = s_f;    red[wid][7] = s_f2;
    }
    __syncthreads();

    if (tid == 0) {
        float t_curv = 0.f, t_cnt = 0.f, t_vd = 0.f, t_ad = 0.f;
        float t_sp = 0.f, t_sp2 = 0.f, t_f = 0.f, t_f2 = 0.f;
        #pragma unroll
        for (int w = 0; w < 8; ++w) {
            t_curv += red[w][0]; t_cnt += red[w][1];
            t_vd   += red[w][2]; t_ad  += red[w][3];
            t_sp   += red[w][4]; t_sp2 += red[w][5];
            t_f    += red[w][6]; t_f2  += red[w][7];
        }

        const float path_curvature = (t_cnt > 0.f) ? (t_curv / t_cnt) : 0.f;

        const float denom = 2.0f * (float)(T_LEN - 1);
        const float velocity_smoothness = 1.0f / (1.0f + t_vd / denom);
        const float acceleration_jerk   = t_ad / denom;

        const float msp = t_sp / (float)T_LEN;
        float var_sp = t_sp2 / (float)T_LEN - msp * msp;
        if (var_sp < 0.f) var_sp = 0.f;
        const float movement_rhythm = sqrtf(var_sp) / (msp + EPS_MEAN);

        const float mf = t_f / (float)T_LEN;
        float var_f = t_f2 / (float)T_LEN - mf * mf;
        if (var_f < 0.f) var_f = 0.f;
        const float force_modulation = sqrtf(var_f) / (mf + EPS_MEAN);

        float* o = out + tr * 5;
        o[0] = path_curvature;
        o[1] = velocity_smoothness;
        o[2] = acceleration_jerk;
        o[3] = movement_rhythm;
        o[4] = force_modulation;
    }
}

extern "C" void kernel_launch(void* const* d_in, const int* in_sizes, int n_in,
                              void* d_out, int out_size) {
    const float4* traj = (const float4*)d_in[0];
    float* out = (float*)d_out;
    signature_kernel<<<N_TRAJ, 256>>>(traj, out);
}